// round 3
// baseline (speedup 1.0000x reference)
#include <cuda_runtime.h>
#include <cuda_bf16.h>
#include <stdint.h>

// ---------------------------------------------------------------------------
// GCN layer: out = scatter_sum(y[src] -> dst) + bias, where y = x @ W^T
// Inputs (metadata order; harness dtype mapping is float32/int32/bf16, so the
// reference's int64 tensors arrive as int32):
//   0: x          float32 [N, 64]
//   1: W          float32 [64, 64]
//   2: bias       float32 [64]
//   3: edge_index int32   [2, E]
//   4: counts     int32   [N]      (unused layout hint)
//   5: out_edge   int32   [E]      (unused layout hint)
//   6: layer_i    int32   scalar   (unused)
// Output: float32 [N, 64]
// ---------------------------------------------------------------------------

#define D 64
#define MAX_N 100000

// Scratch for y = x @ W^T (device-global: no allocation allowed).
// 16B-aligned for float4 access.
__device__ __align__(16) float g_y[(size_t)MAX_N * D];

// ---------------------------------------------------------------------------
// Kernel 1: y = x @ W^T.  One block = 16 rows x 64 cols, 256 threads,
// each thread computes a float4 of outputs for one row.
// ---------------------------------------------------------------------------
__global__ __launch_bounds__(256) void gemm_xWT(
    const float* __restrict__ x, const float* __restrict__ W,
    float* __restrict__ y, int N)
{
    __shared__ float sWt[D][D + 4];   // sWt[k][o] = W[o][k]  (transposed, padded)
    __shared__ float sx[16][D];

    const int tid = threadIdx.x;

    // Load + transpose W (4096 elems, 16 per thread)
    #pragma unroll
    for (int i = tid; i < D * D; i += 256) {
        int o = i >> 6, k = i & 63;
        sWt[k][o] = W[i];
    }

    const int row0 = blockIdx.x * 16;
    // Load 16 rows of x as float4 (16*64 floats = 256 float4)
    {
        int r = tid >> 4;            // 0..15
        int c4 = tid & 15;           // 0..15 (float4 index)
        int row = row0 + r;
        float4 v = make_float4(0.f, 0.f, 0.f, 0.f);
        if (row < N) v = reinterpret_cast<const float4*>(x)[(size_t)row * 16 + c4];
        reinterpret_cast<float4*>(&sx[r][0])[c4] = v;
    }
    __syncthreads();

    const int ty = tid >> 4;         // row within tile 0..15
    const int tx = tid & 15;         // col group 0..15 (4 cols each)
    const int row = row0 + ty;

    float4 acc = make_float4(0.f, 0.f, 0.f, 0.f);
    #pragma unroll
    for (int k = 0; k < D; k++) {
        float xv = sx[ty][k];
        float4 w = *reinterpret_cast<const float4*>(&sWt[k][tx * 4]);
        acc.x = fmaf(xv, w.x, acc.x);
        acc.y = fmaf(xv, w.y, acc.y);
        acc.z = fmaf(xv, w.z, acc.z);
        acc.w = fmaf(xv, w.w, acc.w);
    }
    if (row < N) {
        reinterpret_cast<float4*>(y)[(size_t)row * 16 + tx] = acc;
    }
}

// ---------------------------------------------------------------------------
// Kernel 2: out[n][d] = bias[d]   (output is poisoned; atomics accumulate on top)
// ---------------------------------------------------------------------------
__global__ __launch_bounds__(256) void init_bias(
    float* __restrict__ out, const float* __restrict__ bias, long long total4)
{
    __shared__ float4 sb[16];
    if (threadIdx.x < 16)
        sb[threadIdx.x] = reinterpret_cast<const float4*>(bias)[threadIdx.x];
    __syncthreads();
    long long i = (long long)blockIdx.x * blockDim.x + threadIdx.x;
    long long stride = (long long)gridDim.x * blockDim.x;
    for (; i < total4; i += stride)
        reinterpret_cast<float4*>(out)[i] = sb[i & 15];
}

// ---------------------------------------------------------------------------
// Kernel 3: edge scatter. Thread t handles (edge = t/16, chunk = t%16):
//   out[dst][chunk*4 .. +3] += y[src][chunk*4 .. +3]   via red.global.add.v4.f32
// Lanes 0..15 of a half-warp read one edge's 256B row -> coalesced.
// ---------------------------------------------------------------------------
__global__ __launch_bounds__(256) void scatter_edges(
    const int* __restrict__ ei, const float* __restrict__ y,
    float* __restrict__ out, long long E, int N)
{
    long long t = (long long)blockIdx.x * blockDim.x + threadIdx.x;
    long long e = t >> 4;
    int c = (int)(t & 15);
    if (e >= E) return;

    int src = __ldg(&ei[e]);
    int dst = __ldg(&ei[E + e]);
    // Guard: if the dtype assumption is ever wrong, fail soft (rel_err signal)
    // instead of an illegal access.
    if (((unsigned)src >= (unsigned)N) | ((unsigned)dst >= (unsigned)N)) return;

    float4 v = __ldg(reinterpret_cast<const float4*>(y) + (size_t)src * 16 + c);
    float4* p = reinterpret_cast<float4*>(out) + (size_t)dst * 16 + c;
    asm volatile("red.global.add.v4.f32 [%0], {%1,%2,%3,%4};"
                 :: "l"(p), "f"(v.x), "f"(v.y), "f"(v.z), "f"(v.w)
                 : "memory");
}

// ---------------------------------------------------------------------------
extern "C" void kernel_launch(void* const* d_in, const int* in_sizes, int n_in,
                              void* d_out, int out_size)
{
    const float* x    = (const float*)d_in[0];
    const float* W    = (const float*)d_in[1];
    const float* bias = (const float*)d_in[2];
    const int*   ei   = (const int*)d_in[3];

    const int       N = in_sizes[0] / D;
    const long long E = (long long)in_sizes[3] / 2;
    float* out = (float*)d_out;

    float* y;
    cudaGetSymbolAddress((void**)&y, g_y);

    // 1) y = x @ W^T
    int gemm_blocks = (N + 15) / 16;
    gemm_xWT<<<gemm_blocks, 256>>>(x, W, y, N);

    // 2) out = bias (broadcast)
    long long total4 = (long long)N * 16;
    int init_blocks = (int)((total4 + 255) / 256);
    if (init_blocks > 8192) init_blocks = 8192;
    init_bias<<<init_blocks, 256>>>(out, bias, total4);

    // 3) scatter-add over edges
    long long work = E * 16;
    int sc_blocks = (int)((work + 255) / 256);
    scatter_edges<<<sc_blocks, 256>>>(ei, y, out, E, N);
}

// round 5
// speedup vs baseline: 1.8723x; 1.8723x over previous
#include <cuda_runtime.h>
#include <cuda_bf16.h>
#include <stdint.h>

// ---------------------------------------------------------------------------
// GCN layer: out = scatter_sum(y[src] -> dst) + bias, where y = x @ W^T
// Inputs (int64 tensors arrive as int32 per harness dtype mapping):
//   0: x float32 [N,64]  1: W float32 [64,64]  2: bias float32 [64]
//   3: edge_index int32 [2,E]  4..6: unused hints
// Output: float32 [N, 64]
//
// Strategy:
//   1) gemm_xWT     : register-tiled 4x4 per thread (FFMA-bound, not LDS-bound)
//   2) zero_deg     : reset CSR degree counters + overflow counter
//   3) build_csr    : slot src ids into per-dst lists (cap 64, overflow -> list)
//   4) gather_csr   : per-dst accumulate (single overwrite, no atomics, +bias)
//   5) fallback     : atomic scatter for overflow edges (statistically empty)
// ---------------------------------------------------------------------------

#define D 64
#define MAX_N 100000
#define CAP 64
#define OVF_MAX 8192

__device__ __align__(16) float g_y[(size_t)MAX_N * D];
__device__ int g_deg[MAX_N];
__device__ int g_adj[(size_t)MAX_N * CAP];
__device__ int g_ovf_cnt;
__device__ int g_ovf[OVF_MAX];

// ---------------------------------------------------------------------------
// Kernel 1: y = x @ W^T. Block = 64 rows x 64 cols, 256 threads.
// Thread (ty=tid>>4, tx=tid&15) computes rows {ty, ty+16, ty+32, ty+48},
// cols [tx*4, tx*4+4). Per k: 1 LDS.128 (w) + 4 broadcast LDS (x) + 16 FFMA.
// ---------------------------------------------------------------------------
__global__ __launch_bounds__(256) void gemm_xWT(
    const float* __restrict__ x, const float* __restrict__ W,
    float* __restrict__ y, int N)
{
    __shared__ float sWt[D][D + 4];   // sWt[k][o] = W[o][k]
    __shared__ float sx[64][D];

    const int tid = threadIdx.x;

    #pragma unroll
    for (int i = tid; i < D * D; i += 256)
        sWt[i & 63][i >> 6] = W[i];

    const int row0 = blockIdx.x * 64;
    #pragma unroll
    for (int it = 0; it < 4; it++) {
        int j = tid + it * 256;          // 0..1023 float4 slots
        int r = j >> 4, c4 = j & 15;
        int row = row0 + r;
        float4 v = make_float4(0.f, 0.f, 0.f, 0.f);
        if (row < N) v = reinterpret_cast<const float4*>(x)[(size_t)row * 16 + c4];
        reinterpret_cast<float4*>(&sx[r][0])[c4] = v;
    }
    __syncthreads();

    const int tx = tid & 15;
    const int ty = tid >> 4;

    float4 a0 = make_float4(0.f,0.f,0.f,0.f);
    float4 a1 = a0, a2 = a0, a3 = a0;

    #pragma unroll 8
    for (int k = 0; k < D; k++) {
        float4 w = *reinterpret_cast<const float4*>(&sWt[k][tx * 4]);
        float x0 = sx[ty      ][k];
        float x1 = sx[ty + 16][k];
        float x2 = sx[ty + 32][k];
        float x3 = sx[ty + 48][k];
        a0.x = fmaf(x0, w.x, a0.x); a0.y = fmaf(x0, w.y, a0.y);
        a0.z = fmaf(x0, w.z, a0.z); a0.w = fmaf(x0, w.w, a0.w);
        a1.x = fmaf(x1, w.x, a1.x); a1.y = fmaf(x1, w.y, a1.y);
        a1.z = fmaf(x1, w.z, a1.z); a1.w = fmaf(x1, w.w, a1.w);
        a2.x = fmaf(x2, w.x, a2.x); a2.y = fmaf(x2, w.y, a2.y);
        a2.z = fmaf(x2, w.z, a2.z); a2.w = fmaf(x2, w.w, a2.w);
        a3.x = fmaf(x3, w.x, a3.x); a3.y = fmaf(x3, w.y, a3.y);
        a3.z = fmaf(x3, w.z, a3.z); a3.w = fmaf(x3, w.w, a3.w);
    }

    float4* y4 = reinterpret_cast<float4*>(y);
    int r0 = row0 + ty;
    if (r0      < N) y4[(size_t)(r0      ) * 16 + tx] = a0;
    if (r0 + 16 < N) y4[(size_t)(r0 + 16) * 16 + tx] = a1;
    if (r0 + 32 < N) y4[(size_t)(r0 + 32) * 16 + tx] = a2;
    if (r0 + 48 < N) y4[(size_t)(r0 + 48) * 16 + tx] = a3;
}

// ---------------------------------------------------------------------------
// Kernel 2: reset degree counters + overflow count
// ---------------------------------------------------------------------------
__global__ __launch_bounds__(256) void zero_deg(int N)
{
    int i = blockIdx.x * 256 + threadIdx.x;
    if (i < N) g_deg[i] = 0;
    if (i == 0) g_ovf_cnt = 0;
}

// ---------------------------------------------------------------------------
// Kernel 3: CSR build. One thread per edge: claim a slot in dst's list.
// ---------------------------------------------------------------------------
__global__ __launch_bounds__(256) void build_csr(
    const int* __restrict__ ei, int E, int N)
{
    int e = blockIdx.x * 256 + threadIdx.x;
    if (e >= E) return;
    int src = __ldg(&ei[e]);
    int dst = __ldg(&ei[E + e]);
    if (((unsigned)src >= (unsigned)N) | ((unsigned)dst >= (unsigned)N)) return;
    int pos = atomicAdd(&g_deg[dst], 1);
    if (pos < CAP) {
        g_adj[(size_t)dst * CAP + pos] = src;
    } else {
        int i = atomicAdd(&g_ovf_cnt, 1);
        if (i < OVF_MAX) g_ovf[i] = e;
    }
}

// ---------------------------------------------------------------------------
// Kernel 4: gather. 16 threads per dst (thread c owns float4 chunk c).
// Single write per output row, bias folded in, no atomics.
// ---------------------------------------------------------------------------
__global__ __launch_bounds__(256) void gather_csr(
    const float* __restrict__ bias, float* __restrict__ out, int N)
{
    int d = blockIdx.x * 16 + (threadIdx.x >> 4);
    int c = threadIdx.x & 15;
    if (d >= N) return;

    int cnt = g_deg[d];
    if (cnt > CAP) cnt = CAP;

    float4 acc = __ldg(reinterpret_cast<const float4*>(bias) + c);
    const int* lst = &g_adj[(size_t)d * CAP];
    const float4* y4 = reinterpret_cast<const float4*>(g_y);

    int src = (cnt > 0) ? __ldg(&lst[0]) : 0;
    for (int i = 0; i < cnt; i++) {
        int nsrc = (i + 1 < cnt) ? __ldg(&lst[i + 1]) : 0;   // prefetch
        float4 v = __ldg(y4 + (size_t)src * 16 + c);
        acc.x += v.x; acc.y += v.y; acc.z += v.z; acc.w += v.w;
        src = nsrc;
    }
    reinterpret_cast<float4*>(out)[(size_t)d * 16 + c] = acc;
}

// ---------------------------------------------------------------------------
// Kernel 5: overflow fallback (normally zero work). Fixed grid; loops over
// g_ovf_cnt * 16 chunks with vector reductions on top of gathered output.
// ---------------------------------------------------------------------------
__global__ __launch_bounds__(256) void fallback_scatter(
    const int* __restrict__ ei, int E, float* __restrict__ out, int N)
{
    int cnt = g_ovf_cnt;
    if (cnt > OVF_MAX) cnt = OVF_MAX;
    int work = cnt * 16;
    for (int t = blockIdx.x * 256 + threadIdx.x; t < work;
         t += gridDim.x * 256) {
        int e = g_ovf[t >> 4];
        int c = t & 15;
        int src = __ldg(&ei[e]);
        int dst = __ldg(&ei[E + e]);
        if (((unsigned)src >= (unsigned)N) | ((unsigned)dst >= (unsigned)N)) continue;
        float4 v = __ldg(reinterpret_cast<const float4*>(g_y) + (size_t)src * 16 + c);
        float4* p = reinterpret_cast<float4*>(out) + (size_t)dst * 16 + c;
        asm volatile("red.global.add.v4.f32 [%0], {%1,%2,%3,%4};"
                     :: "l"(p), "f"(v.x), "f"(v.y), "f"(v.z), "f"(v.w)
                     : "memory");
    }
}

// ---------------------------------------------------------------------------
extern "C" void kernel_launch(void* const* d_in, const int* in_sizes, int n_in,
                              void* d_out, int out_size)
{
    const float* x    = (const float*)d_in[0];
    const float* W    = (const float*)d_in[1];
    const float* bias = (const float*)d_in[2];
    const int*   ei   = (const int*)d_in[3];

    const int N = in_sizes[0] / D;
    const int E = in_sizes[3] / 2;
    float* out = (float*)d_out;

    float* y;
    cudaGetSymbolAddress((void**)&y, g_y);

    // CSR build (independent of GEMM)
    zero_deg<<<(N + 255) / 256, 256>>>(N);
    build_csr<<<(E + 255) / 256, 256>>>(ei, E, N);

    // y = x @ W^T
    gemm_xWT<<<(N + 63) / 64, 256>>>(x, W, y, N);

    // dst-centric accumulate (+bias), then overflow fixup
    gather_csr<<<(N + 15) / 16, 256>>>(bias, out, N);
    fallback_scatter<<<64, 256>>>(ei, E, out, N);
}

// round 6
// speedup vs baseline: 1.9339x; 1.0329x over previous
#include <cuda_runtime.h>
#include <cuda_bf16.h>
#include <stdint.h>

// ---------------------------------------------------------------------------
// GCN layer: out = scatter_sum(y[src] -> dst) + bias, where y = x @ W^T
// Inputs (int64 tensors arrive as int32 per harness dtype mapping):
//   0: x float32 [N,64]  1: W float32 [64,64]  2: bias float32 [64]
//   3: edge_index int32 [2,E]  4..6: unused hints
// Output: float32 [N, 64]
//
// Pipeline:
//   1) zero_deg        : reset CSR degree counters + overflow counter (tiny)
//   2) fused_gemm_build: blocks [0,Gg) compute y = x@W^T (4x4 register tile);
//                        blocks [Gg,..) slot edges into per-dst CSR lists.
//                        Independent workloads co-reside -> max() not sum().
//   3) gather_csr      : per-dst accumulate from L2-resident y (+bias),
//                        single overwrite, no atomics, 2-edge unroll.
//   4) fallback_scatter: atomic fixup for CAP overflow (statistically empty).
// ---------------------------------------------------------------------------

#define D 64
#define MAX_N 100000
#define CAP 64
#define OVF_MAX 8192

__device__ __align__(16) float g_y[(size_t)MAX_N * D];
__device__ int g_deg[MAX_N];
__device__ int g_adj[(size_t)MAX_N * CAP];
__device__ int g_ovf_cnt;
__device__ int g_ovf[OVF_MAX];

// ---------------------------------------------------------------------------
// Kernel 1: reset degree counters + overflow count
// ---------------------------------------------------------------------------
__global__ __launch_bounds__(256) void zero_deg(int N)
{
    int i = blockIdx.x * 256 + threadIdx.x;
    if (i < N) g_deg[i] = 0;
    if (i == 0) g_ovf_cnt = 0;
}

// ---------------------------------------------------------------------------
// Kernel 2: fused GEMM + CSR build.
//   blockIdx.x <  gemmBlocks : 64-row GEMM tile (256 thr, 4x4 register tile)
//   blockIdx.x >= gemmBlocks : 256 edges -> CSR slots
// ---------------------------------------------------------------------------
__global__ __launch_bounds__(256) void fused_gemm_build(
    const float* __restrict__ x, const float* __restrict__ W,
    float* __restrict__ y, int N,
    const int* __restrict__ ei, int E, int gemmBlocks)
{
    const int tid = threadIdx.x;

    if (blockIdx.x >= gemmBlocks) {
        // ----- CSR build branch -----
        int e = (blockIdx.x - gemmBlocks) * 256 + tid;
        if (e >= E) return;
        int src = __ldg(&ei[e]);
        int dst = __ldg(&ei[E + e]);
        if (((unsigned)src >= (unsigned)N) | ((unsigned)dst >= (unsigned)N)) return;
        int pos = atomicAdd(&g_deg[dst], 1);
        if (pos < CAP) {
            g_adj[(size_t)dst * CAP + pos] = src;
        } else {
            int i = atomicAdd(&g_ovf_cnt, 1);
            if (i < OVF_MAX) g_ovf[i] = e;
        }
        return;
    }

    // ----- GEMM branch: y = x @ W^T -----
    __shared__ float sWt[D][D + 4];   // sWt[k][o] = W[o][k]
    __shared__ float sx[64][D];

    #pragma unroll
    for (int i = tid; i < D * D; i += 256)
        sWt[i & 63][i >> 6] = W[i];

    const int row0 = blockIdx.x * 64;
    #pragma unroll
    for (int it = 0; it < 4; it++) {
        int j = tid + it * 256;          // 0..1023 float4 slots
        int r = j >> 4, c4 = j & 15;
        int row = row0 + r;
        float4 v = make_float4(0.f, 0.f, 0.f, 0.f);
        if (row < N) v = reinterpret_cast<const float4*>(x)[(size_t)row * 16 + c4];
        reinterpret_cast<float4*>(&sx[r][0])[c4] = v;
    }
    __syncthreads();

    const int tx = tid & 15;
    const int ty = tid >> 4;

    float4 a0 = make_float4(0.f,0.f,0.f,0.f);
    float4 a1 = a0, a2 = a0, a3 = a0;

    #pragma unroll 8
    for (int k = 0; k < D; k++) {
        float4 w = *reinterpret_cast<const float4*>(&sWt[k][tx * 4]);
        float x0 = sx[ty      ][k];
        float x1 = sx[ty + 16][k];
        float x2 = sx[ty + 32][k];
        float x3 = sx[ty + 48][k];
        a0.x = fmaf(x0, w.x, a0.x); a0.y = fmaf(x0, w.y, a0.y);
        a0.z = fmaf(x0, w.z, a0.z); a0.w = fmaf(x0, w.w, a0.w);
        a1.x = fmaf(x1, w.x, a1.x); a1.y = fmaf(x1, w.y, a1.y);
        a1.z = fmaf(x1, w.z, a1.z); a1.w = fmaf(x1, w.w, a1.w);
        a2.x = fmaf(x2, w.x, a2.x); a2.y = fmaf(x2, w.y, a2.y);
        a2.z = fmaf(x2, w.z, a2.z); a2.w = fmaf(x2, w.w, a2.w);
        a3.x = fmaf(x3, w.x, a3.x); a3.y = fmaf(x3, w.y, a3.y);
        a3.z = fmaf(x3, w.z, a3.z); a3.w = fmaf(x3, w.w, a3.w);
    }

    float4* y4 = reinterpret_cast<float4*>(y);
    int r0 = row0 + ty;
    if (r0      < N) y4[(size_t)(r0      ) * 16 + tx] = a0;
    if (r0 + 16 < N) y4[(size_t)(r0 + 16) * 16 + tx] = a1;
    if (r0 + 32 < N) y4[(size_t)(r0 + 32) * 16 + tx] = a2;
    if (r0 + 48 < N) y4[(size_t)(r0 + 48) * 16 + tx] = a3;
}

// ---------------------------------------------------------------------------
// Kernel 3: gather. 16 threads per dst (thread c owns float4 chunk c).
// Single write per output row, bias folded in, no atomics. 2-edge unroll
// for MLP=2 per thread and halved loop overhead.
// ---------------------------------------------------------------------------
__global__ __launch_bounds__(256) void gather_csr(
    const float* __restrict__ bias, float* __restrict__ out, int N)
{
    int d = blockIdx.x * 16 + (threadIdx.x >> 4);
    int c = threadIdx.x & 15;
    if (d >= N) return;

    int cnt = g_deg[d];
    if (cnt > CAP) cnt = CAP;

    float4 acc = __ldg(reinterpret_cast<const float4*>(bias) + c);
    const int* lst = &g_adj[(size_t)d * CAP];
    const float4* y4 = reinterpret_cast<const float4*>(g_y);

    float4 acc2 = make_float4(0.f, 0.f, 0.f, 0.f);
    int i = 0;
    for (; i + 2 <= cnt; i += 2) {
        int s0 = __ldg(&lst[i]);
        int s1 = __ldg(&lst[i + 1]);
        float4 v0 = __ldg(y4 + (size_t)s0 * 16 + c);
        float4 v1 = __ldg(y4 + (size_t)s1 * 16 + c);
        acc.x  += v0.x; acc.y  += v0.y; acc.z  += v0.z; acc.w  += v0.w;
        acc2.x += v1.x; acc2.y += v1.y; acc2.z += v1.z; acc2.w += v1.w;
    }
    if (i < cnt) {
        int s0 = __ldg(&lst[i]);
        float4 v0 = __ldg(y4 + (size_t)s0 * 16 + c);
        acc.x += v0.x; acc.y += v0.y; acc.z += v0.z; acc.w += v0.w;
    }
    acc.x += acc2.x; acc.y += acc2.y; acc.z += acc2.z; acc.w += acc2.w;

    reinterpret_cast<float4*>(out)[(size_t)d * 16 + c] = acc;
}

// ---------------------------------------------------------------------------
// Kernel 4: overflow fallback (normally zero work).
// ---------------------------------------------------------------------------
__global__ __launch_bounds__(256) void fallback_scatter(
    const int* __restrict__ ei, int E, float* __restrict__ out, int N)
{
    int cnt = g_ovf_cnt;
    if (cnt > OVF_MAX) cnt = OVF_MAX;
    int work = cnt * 16;
    for (int t = blockIdx.x * 256 + threadIdx.x; t < work;
         t += gridDim.x * 256) {
        int e = g_ovf[t >> 4];
        int c = t & 15;
        int src = __ldg(&ei[e]);
        int dst = __ldg(&ei[E + e]);
        if (((unsigned)src >= (unsigned)N) | ((unsigned)dst >= (unsigned)N)) continue;
        float4 v = __ldg(reinterpret_cast<const float4*>(g_y) + (size_t)src * 16 + c);
        float4* p = reinterpret_cast<float4*>(out) + (size_t)dst * 16 + c;
        asm volatile("red.global.add.v4.f32 [%0], {%1,%2,%3,%4};"
                     :: "l"(p), "f"(v.x), "f"(v.y), "f"(v.z), "f"(v.w)
                     : "memory");
    }
}

// ---------------------------------------------------------------------------
extern "C" void kernel_launch(void* const* d_in, const int* in_sizes, int n_in,
                              void* d_out, int out_size)
{
    const float* x    = (const float*)d_in[0];
    const float* W    = (const float*)d_in[1];
    const float* bias = (const float*)d_in[2];
    const int*   ei   = (const int*)d_in[3];

    const int N = in_sizes[0] / D;
    const int E = in_sizes[3] / 2;
    float* out = (float*)d_out;

    float* y;
    cudaGetSymbolAddress((void**)&y, g_y);

    const int gemmBlocks  = (N + 63) / 64;
    const int buildBlocks = (E + 255) / 256;

    zero_deg<<<(N + 255) / 256, 256>>>(N);
    fused_gemm_build<<<gemmBlocks + buildBlocks, 256>>>(x, W, y, N, ei, E, gemmBlocks);
    gather_csr<<<(N + 15) / 16, 256>>>(bias, out, N);
    fallback_scatter<<<64, 256>>>(ei, E, out, N);
}